// round 8
// baseline (speedup 1.0000x reference)
#include <cuda_runtime.h>
#include <cstdint>

#define HIDDEN 1024
#define SLOTS 16
#define BSZ 512
#define SEGLEN 256
#define TT 16            // t-tile in fused attention
#define SCALE 0.03125f   // 1/sqrt(1024)

// ---------------- scratch (device globals; no allocation) ----------------
__device__ float g_q1[SLOTS * HIDDEN];
__device__ float g_q2[SLOTS * HIDDEN];
__device__ float g_w2[HIDDEN * HIDDEN];
__device__ float g_b2[HIDDEN];
__device__ float g_y[(size_t)BSZ * SLOTS * HIDDEN];      // [b][s][d]

// ---------------- helpers ----------------
__device__ __forceinline__ float tf32r(float x) {
    uint32_t u;
    asm("cvt.rna.tf32.f32 %0, %1;" : "=r"(u) : "f"(x));
    return __uint_as_float(u);
}
__device__ __forceinline__ float4 tf32r4(float4 v) {
    return make_float4(tf32r(v.x), tf32r(v.y), tf32r(v.z), tf32r(v.w));
}
__device__ __forceinline__ uint32_t f2u(float x) { return __float_as_uint(x); }

__device__ __forceinline__ void mma8(float* c, const uint32_t* a, const uint32_t* b) {
    asm volatile(
        "mma.sync.aligned.m16n8k8.row.col.f32.tf32.tf32.f32 "
        "{%0,%1,%2,%3},{%4,%5,%6,%7},{%8,%9},{%0,%1,%2,%3};"
        : "+f"(c[0]), "+f"(c[1]), "+f"(c[2]), "+f"(c[3])
        : "r"(a[0]), "r"(a[1]), "r"(a[2]), "r"(a[3]), "r"(b[0]), "r"(b[1]));
}

__device__ __forceinline__ uint32_t smem_u32(const void* p) {
    uint32_t a;
    asm("{ .reg .u64 t; cvta.to.shared.u64 t, %1; cvt.u32.u64 %0, t; }" : "=r"(a) : "l"(p));
    return a;
}
__device__ __forceinline__ void cpasync16(uint32_t dst, const void* src) {
    asm volatile("cp.async.cg.shared.global [%0], [%1], 16;" :: "r"(dst), "l"(src));
}
#define CP_COMMIT() asm volatile("cp.async.commit_group;")
#define CP_WAIT(n)  asm volatile("cp.async.wait_group %0;" :: "n"(n))

// ---------------- multi-stage cp.async tf32 GEMM ----------------
// C[m,n] = sum_k A[m,k] * (BT ? B[n,k] : B[k,n])  (+ bias[n] if BIAS)
// CVT: RNA-convert smem tiles in place before compute (unbiased tf32).
// Otherwise raw fp32 -> mma hardware RZ (only safe if inputs tf32-exact).
template <int BM, int BN, int BK, int WM, int WN, int STAGES,
          bool BT, bool BIAS, bool RNA, bool CVT, int MINCTA>
__global__ void __launch_bounds__(WM * WN * 32, MINCTA) gemm_cpa(
    const float* __restrict__ A, const float* __restrict__ B,
    float* __restrict__ C, const float* __restrict__ bias,
    int M, int N, int K)
{
    constexpr int THREADS = WM * WN * 32;
    constexpr int LA = BK + 8;
    constexpr int LB = BN + 8;
    constexpr int ASZ = BM * LA;
    constexpr int BSZE = BT ? BN * LA : BK * LB;
    constexpr int AITER = BM * BK / 4 / THREADS;
    constexpr int BITER = BN * BK / 4 / THREADS;

    extern __shared__ float sm[];

    const int tid  = threadIdx.x;
    const int lane = tid & 31;
    const int warp = tid >> 5;
    const int r  = lane >> 2;
    const int cq = lane & 3;
    const int wm = warp / WN, wn = warp % WN;
    constexpr int WTM = BM / WM, WTN = BN / WN;
    constexpr int MI = WTM / 16, NI = WTN / 8;
    const int mW = wm * WTM, nW = wn * WTN;
    const int m0 = blockIdx.y * BM;
    const int n0 = blockIdx.x * BN;

    float acc[MI][NI][4];
    #pragma unroll
    for (int mi = 0; mi < MI; mi++)
        #pragma unroll
        for (int ni = 0; ni < NI; ni++)
            #pragma unroll
            for (int j = 0; j < 4; j++) acc[mi][ni][j] = 0.0f;

    auto issue = [&](int k0, int buf) {
        float* As = sm + buf * (ASZ + BSZE);
        float* Bs = As + ASZ;
        uint32_t ab = smem_u32(As);
        uint32_t bb = smem_u32(Bs);
        #pragma unroll
        for (int i = 0; i < AITER; i++) {
            int idx = i * THREADS + tid;
            int row = idx / (BK / 4), k4 = idx % (BK / 4);
            cpasync16(ab + (row * LA + k4 * 4) * 4,
                      A + (long)(m0 + row) * K + k0 + k4 * 4);
        }
        if constexpr (BT) {
            #pragma unroll
            for (int i = 0; i < BITER; i++) {
                int idx = i * THREADS + tid;
                int row = idx / (BK / 4), k4 = idx % (BK / 4);
                cpasync16(bb + (row * LA + k4 * 4) * 4,
                          B + (long)(n0 + row) * K + k0 + k4 * 4);
            }
        } else {
            #pragma unroll
            for (int i = 0; i < BITER; i++) {
                int idx = i * THREADS + tid;
                int row = idx / (BN / 4), n4 = idx % (BN / 4);
                cpasync16(bb + (row * LB + n4 * 4) * 4,
                          B + (long)(k0 + row) * N + n0 + n4 * 4);
            }
        }
        CP_COMMIT();
    };
    auto compute = [&](int buf) {
        const float* As = sm + buf * (ASZ + BSZE);
        const float* Bs = As + ASZ;
        #pragma unroll
        for (int k8 = 0; k8 < BK / 8; k8++) {
            uint32_t af[MI][4], bf[NI][2];
            #pragma unroll
            for (int mi = 0; mi < MI; mi++) {
                int mr = mW + mi * 16 + r;
                af[mi][0] = f2u(As[mr * LA + k8 * 8 + cq]);
                af[mi][1] = f2u(As[(mr + 8) * LA + k8 * 8 + cq]);
                af[mi][2] = f2u(As[mr * LA + k8 * 8 + cq + 4]);
                af[mi][3] = f2u(As[(mr + 8) * LA + k8 * 8 + cq + 4]);
            }
            #pragma unroll
            for (int ni = 0; ni < NI; ni++) {
                int nc = nW + ni * 8 + r;
                if constexpr (BT) {
                    bf[ni][0] = f2u(Bs[nc * LA + k8 * 8 + cq]);
                    bf[ni][1] = f2u(Bs[nc * LA + k8 * 8 + cq + 4]);
                } else {
                    bf[ni][0] = f2u(Bs[(k8 * 8 + cq) * LB + nc]);
                    bf[ni][1] = f2u(Bs[(k8 * 8 + cq + 4) * LB + nc]);
                }
            }
            #pragma unroll
            for (int mi = 0; mi < MI; mi++)
                #pragma unroll
                for (int ni = 0; ni < NI; ni++)
                    mma8(acc[mi][ni], af[mi], bf[ni]);
        }
    };

    const int NTILES = K / BK;
    #pragma unroll
    for (int s = 0; s < STAGES - 1; s++) issue(s * BK, s);

    for (int t = 0; t < NTILES; t++) {
        if (t + STAGES - 1 < NTILES) {
            issue((t + STAGES - 1) * BK, (t + STAGES - 1) % STAGES);
            CP_WAIT(STAGES - 1);
        } else {
            int rem = NTILES - 1 - t;   // ≤ STAGES-2
            if constexpr (STAGES >= 4) { if (rem == 2) CP_WAIT(2); }
            if (rem == 1) CP_WAIT(1);
            else if (rem == 0) CP_WAIT(0);
        }
        __syncthreads();
        if constexpr (CVT) {
            // unbiased RNA tf32 conversion in place (padding junk harmless)
            float* base = sm + (t % STAGES) * (ASZ + BSZE);
            constexpr int TOT4 = (ASZ + BSZE) / 4;
            for (int i = tid; i < TOT4; i += THREADS) {
                float4* p = (float4*)base + i;
                *p = tf32r4(*p);
            }
            __syncthreads();
        }
        compute(t % STAGES);
        __syncthreads();
    }

    #pragma unroll
    for (int mi = 0; mi < MI; mi++) {
        int row = m0 + mW + mi * 16 + r;
        #pragma unroll
        for (int ni = 0; ni < NI; ni++) {
            int col = n0 + nW + ni * 8 + 2 * cq;
            float2 v0 = make_float2(acc[mi][ni][0], acc[mi][ni][1]);
            float2 v1 = make_float2(acc[mi][ni][2], acc[mi][ni][3]);
            if constexpr (BIAS) {
                float b0 = bias[col], b1 = bias[col + 1];
                v0.x += b0; v0.y += b1; v1.x += b0; v1.y += b1;
            }
            if constexpr (RNA) {
                v0.x = tf32r(v0.x); v0.y = tf32r(v0.y);
                v1.x = tf32r(v1.x); v1.y = tf32r(v1.y);
            }
            *(float2*)(C + (long)row * N + col) = v0;
            *(float2*)(C + (long)(row + 8) * N + col) = v1;
        }
    }
}

// ---------------- b2[e] = dot(Wo[e,:], bv) + bo[e] ----------------
__global__ void __launch_bounds__(256) k_b2(const float* __restrict__ Wo,
                                            const float* __restrict__ bv,
                                            const float* __restrict__ bo) {
    int e = blockIdx.x * 256 + threadIdx.x;
    const float4* wo = (const float4*)(Wo + (long)e * HIDDEN);
    const float4* bvv = (const float4*)bv;
    float acc = 0.0f;
    #pragma unroll 4
    for (int i = 0; i < HIDDEN / 4; i++) {
        float4 a = wo[i], b = bvv[i];
        acc = fmaf(a.x, b.x, acc); acc = fmaf(a.y, b.y, acc);
        acc = fmaf(a.z, b.z, acc); acc = fmaf(a.w, b.w, acc);
    }
    g_b2[e] = acc + bo[e];
}

// ---------------- fused attention: 512 threads, 3-stage cp.async, Q2 in regs ----------------
#define LQ2 1032
#define OFF_X  0
#define OFF_SP (3 * TT * LQ2)
#define OFF_P  (OFF_SP + 16 * 16 * TT)
#define OFF_M  (OFF_P + 16 * 24)
#define OFF_L  (OFF_M + 16)
#define OFF_SC (OFF_L + 16)
#define OFF_LG (OFF_SC + 16)
#define FUSED_SMEM ((OFF_LG + SEGLEN) * 4)

__global__ void __launch_bounds__(512, 1) fused_attn(
    const float* __restrict__ X, const float* __restrict__ logits,
    float* __restrict__ Y)
{
    extern __shared__ float sm[];
    float* Xs  = sm + OFF_X;
    float* Sp  = sm + OFF_SP;
    float* Ps  = sm + OFF_P;
    float* mS  = sm + OFF_M;
    float* lS  = sm + OFF_L;
    float* scS = sm + OFF_SC;
    float* lgS = sm + OFF_LG;

    const int b    = blockIdx.x;
    const int tid  = threadIdx.x;
    const int lane = tid & 31;
    const int w    = tid >> 5;        // 0..15, d-chunk = [w*64, w*64+64)
    const int r    = lane >> 2;
    const int cq   = lane & 3;
    const float* Xb = X + (long)b * SEGLEN * HIDDEN;

    auto issueX = [&](int it) {
        int buf = it % 3;
        const float* src0 = Xb + (long)it * TT * HIDDEN;
        uint32_t dstb = smem_u32(Xs + buf * TT * LQ2);
        #pragma unroll
        for (int i = 0; i < 8; i++) {
            int idx = i * 512 + tid;          // 4096 float4 per stage
            int row = idx >> 8, c4 = idx & 255;
            cpasync16(dstb + (row * LQ2 + c4 * 4) * 4, src0 + row * HIDDEN + c4 * 4);
        }
        CP_COMMIT();
    };
    issueX(0); issueX(1);

    if (tid < 256) lgS[tid] = logits[(long)b * SEGLEN + tid];
    if (tid < 16) { mS[tid] = -INFINITY; lS[tid] = 0.0f; }

    // Q2 fragments in registers (Q2 is RNA-rounded tf32-exact)
    uint32_t afq[8][4];
    #pragma unroll
    for (int k8 = 0; k8 < 8; k8++) {
        int col = w * 64 + k8 * 8 + cq;
        afq[k8][0] = f2u(__ldg(&g_q2[(long)r * HIDDEN + col]));
        afq[k8][1] = f2u(__ldg(&g_q2[(long)(r + 8) * HIDDEN + col]));
        afq[k8][2] = f2u(__ldg(&g_q2[(long)r * HIDDEN + col + 4]));
        afq[k8][3] = f2u(__ldg(&g_q2[(long)(r + 8) * HIDDEN + col + 4]));
    }

    float acc[8][4];
    #pragma unroll
    for (int ni = 0; ni < 8; ni++)
        #pragma unroll
        for (int j = 0; j < 4; j++) acc[ni][j] = 0.0f;

    __syncthreads();

    const int NT = SEGLEN / TT;   // 16 tiles
    for (int it = 0; it < NT; it++) {
        if (it + 2 < NT) { issueX(it + 2); CP_WAIT(2); }
        else if (NT - 1 - it == 1) CP_WAIT(1);
        else CP_WAIT(0);
        __syncthreads();
        const float* Xt = Xs + (it % 3) * TT * LQ2;

        // ---- scores: warp covers d in [w*64, w*64+64) ----
        {
            float sacc[2][4] = {{0,0,0,0},{0,0,0,0}};
            #pragma unroll
            for (int k8 = 0; k8 < 8; k8++) {
                int kk = w * 64 + k8 * 8;
                uint32_t bf[2][2];
                #pragma unroll
                for (int nt = 0; nt < 2; nt++) {
                    int nc = nt * 8 + r;
                    bf[nt][0] = f2u(Xt[nc * LQ2 + kk + cq]);
                    bf[nt][1] = f2u(Xt[nc * LQ2 + kk + cq + 4]);
                }
                mma8(sacc[0], afq[k8], bf[0]);
                mma8(sacc[1], afq[k8], bf[1]);
            }
            #pragma unroll
            for (int nt = 0; nt < 2; nt++) {
                int c0 = nt * 8 + 2 * cq;
                Sp[(w * 16 + r) * TT + c0]         = sacc[nt][0];
                Sp[(w * 16 + r) * TT + c0 + 1]     = sacc[nt][1];
                Sp[(w * 16 + r + 8) * TT + c0]     = sacc[nt][2];
                Sp[(w * 16 + r + 8) * TT + c0 + 1] = sacc[nt][3];
            }
        }
        __syncthreads();

        // ---- online softmax: thread (s = tid>>4, t = tid&15), tid < 256 ----
        if (tid < 256) {
            int s = tid >> 4, t = tid & 15;
            float accs = 0.0f;
            #pragma unroll
            for (int ww = 0; ww < 16; ww++) accs += Sp[(ww * 16 + s) * TT + t];
            float v = accs * SCALE + lgS[it * TT + t];
            float m_t = v;
            #pragma unroll
            for (int o = 8; o; o >>= 1) m_t = fmaxf(m_t, __shfl_xor_sync(0xffffffffu, m_t, o));
            float m_old = mS[s];
            float newm = fmaxf(m_old, m_t);
            float p = expf(v - newm);
            Ps[s * 24 + t] = tf32r(p);
            float sum = p;
            #pragma unroll
            for (int o = 8; o; o >>= 1) sum += __shfl_xor_sync(0xffffffffu, sum, o);
            if (t == 0) {
                float scale = expf(m_old - newm); // 0 on first tile
                lS[s] = lS[s] * scale + sum;
                mS[s] = newm;
                scS[s] = scale;
            }
        }
        __syncthreads();

        // ---- rescale Y acc, then Y += P @ X_tile ----
        {
            float sc0 = scS[r], sc1 = scS[r + 8];
            #pragma unroll
            for (int ni = 0; ni < 8; ni++) {
                acc[ni][0] *= sc0; acc[ni][1] *= sc0;
                acc[ni][2] *= sc1; acc[ni][3] *= sc1;
            }
            #pragma unroll
            for (int k8 = 0; k8 < 2; k8++) {
                uint32_t af[4];
                af[0] = f2u(Ps[r * 24 + k8 * 8 + cq]);
                af[1] = f2u(Ps[(r + 8) * 24 + k8 * 8 + cq]);
                af[2] = f2u(Ps[r * 24 + k8 * 8 + cq + 4]);
                af[3] = f2u(Ps[(r + 8) * 24 + k8 * 8 + cq + 4]);
                #pragma unroll
                for (int ni = 0; ni < 8; ni++) {
                    int nc = w * 64 + ni * 8 + r;
                    uint32_t bf[2];
                    bf[0] = f2u(Xt[(k8 * 8 + cq) * LQ2 + nc]);
                    bf[1] = f2u(Xt[(k8 * 8 + cq + 4) * LQ2 + nc]);
                    mma8(acc[ni], af, bf);
                }
            }
        }
        __syncthreads();   // protect Xs buffer + Ps/scS/mS/lS before next tile
    }

    // ---- epilogue: Y[b][s][d] = acc / l, RNA-rounded (tf32-exact for next GEMM) ----
    float inv0 = 1.0f / lS[r];
    float inv1 = 1.0f / lS[r + 8];
    float* Y0 = Y + ((long)b * SLOTS + r) * HIDDEN;
    float* Y1 = Y + ((long)b * SLOTS + r + 8) * HIDDEN;
    #pragma unroll
    for (int ni = 0; ni < 8; ni++) {
        int col = w * 64 + ni * 8 + 2 * cq;
        float2 v0 = make_float2(tf32r(acc[ni][0] * inv0), tf32r(acc[ni][1] * inv0));
        float2 v1 = make_float2(tf32r(acc[ni][2] * inv1), tf32r(acc[ni][3] * inv1));
        *(float2*)(Y0 + col) = v0;
        *(float2*)(Y1 + col) = v1;
    }
}

// ---------------- launch ----------------
extern "C" void kernel_launch(void* const* d_in, const int* in_sizes, int n_in,
                              void* d_out, int out_size) {
    const float* X      = (const float*)d_in[0];   // [512,256,1024]
    const float* logits = (const float*)d_in[1];   // [512,256]
    const float* LQ     = (const float*)d_in[2];   // [16,1024]
    const float* Wq     = (const float*)d_in[3];
    const float* bq     = (const float*)d_in[4];
    const float* Wk     = (const float*)d_in[5];
    // d_in[6] = bk: cancels in softmax, unused
    const float* Wv     = (const float*)d_in[7];
    const float* bv     = (const float*)d_in[8];
    const float* Wo     = (const float*)d_in[9];
    const float* bo     = (const float*)d_in[10];
    float* out = (float*)d_out;

    float *q1p, *q2p, *w2p, *b2p, *yp;
    cudaGetSymbolAddress((void**)&q1p, g_q1);
    cudaGetSymbolAddress((void**)&q2p, g_q2);
    cudaGetSymbolAddress((void**)&w2p, g_w2);
    cudaGetSymbolAddress((void**)&b2p, g_b2);
    cudaGetSymbolAddress((void**)&yp,  g_y);

    // smem opt-in (idempotent)
    cudaFuncSetAttribute((const void*)gemm_cpa<16,64,32,1,4,4,true,true,true,true,1>,
                         cudaFuncAttributeMaxDynamicSharedMemorySize, 51200);
    cudaFuncSetAttribute((const void*)gemm_cpa<16,64,32,1,4,4,false,false,true,true,1>,
                         cudaFuncAttributeMaxDynamicSharedMemorySize, 47104);
    cudaFuncSetAttribute((const void*)gemm_cpa<64,64,32,2,2,3,false,false,true,true,1>,
                         cudaFuncAttributeMaxDynamicSharedMemorySize, 58368);
    cudaFuncSetAttribute((const void*)gemm_cpa<128,128,32,2,2,2,true,true,false,false,2>,
                         cudaFuncAttributeMaxDynamicSharedMemorySize, 81920);
    cudaFuncSetAttribute((const void*)fused_attn,
                         cudaFuncAttributeMaxDynamicSharedMemorySize, FUSED_SMEM);

    // 1) q1 = LQ @ Wq^T + bq    [16,1024]   (RNA-converted inputs)
    gemm_cpa<16, 64, 32, 1, 4, 4, true, true, true, true, 1><<<dim3(16, 1), 128, 51200>>>(
        LQ, Wq, q1p, bq, 16, 1024, 1024);
    // 2) Q2 = q1 @ Wk           [16,1024]   (RNA-converted inputs)
    gemm_cpa<16, 64, 32, 1, 4, 4, false, false, true, true, 1><<<dim3(16, 1), 128, 47104>>>(
        q1p, Wk, q2p, nullptr, 16, 1024, 1024);
    // 3) b2 = Wo @ bv + bo
    k_b2<<<4, 256>>>(Wo, bv, bo);
    // 4) W2 = Wo @ Wv           [1024,1024] (RNA-converted inputs)
    gemm_cpa<64, 64, 32, 2, 2, 3, false, false, true, true, 1><<<dim3(16, 16), 128, 58368>>>(
        Wo, Wv, w2p, nullptr, 1024, 1024, 1024);
    // 5) fused attention: Y[b] = softmax(Q2·X^T/32 + logits) @ X   (X read once)
    fused_attn<<<BSZ, 512, FUSED_SMEM>>>(X, logits, yp);
    // 6) out = Y @ W2^T + b2    [8192,1024] (inputs tf32-exact; big warp tile)
    gemm_cpa<128, 128, 32, 2, 2, 2, true, true, false, false, 2><<<dim3(8, 64), 128, 81920>>>(
        yp, w2p, out, b2p, BSZ * SLOTS, HIDDEN, HIDDEN);
}

// round 9
// speedup vs baseline: 1.1360x; 1.1360x over previous
#include <cuda_runtime.h>
#include <cstdint>

#define HIDDEN 1024
#define SLOTS 16
#define BSZ 512
#define SEGLEN 256
#define TT 16            // t-tile in fused attention
#define SCALE 0.03125f   // 1/sqrt(1024)

// ---------------- scratch (device globals; no allocation) ----------------
__device__ float g_lq[SLOTS * HIDDEN];                   // RNA-rounded latent queries
__device__ float g_wq[HIDDEN * HIDDEN];                  // RNA-rounded weights
__device__ float g_wk[HIDDEN * HIDDEN];
__device__ float g_wo[HIDDEN * HIDDEN];
__device__ float g_wv[HIDDEN * HIDDEN];
__device__ float g_q1[SLOTS * HIDDEN];
__device__ float g_q2[SLOTS * HIDDEN];
__device__ float g_w2[HIDDEN * HIDDEN];
__device__ float g_b2[HIDDEN];
__device__ float g_y[(size_t)BSZ * SLOTS * HIDDEN];      // [b][s][d]

// ---------------- helpers ----------------
__device__ __forceinline__ float tf32r(float x) {
    uint32_t u;
    asm("cvt.rna.tf32.f32 %0, %1;" : "=r"(u) : "f"(x));
    return __uint_as_float(u);
}
__device__ __forceinline__ float4 tf32r4(float4 v) {
    return make_float4(tf32r(v.x), tf32r(v.y), tf32r(v.z), tf32r(v.w));
}
__device__ __forceinline__ uint32_t f2u(float x) { return __float_as_uint(x); }

__device__ __forceinline__ void mma8(float* c, const uint32_t* a, const uint32_t* b) {
    asm volatile(
        "mma.sync.aligned.m16n8k8.row.col.f32.tf32.tf32.f32 "
        "{%0,%1,%2,%3},{%4,%5,%6,%7},{%8,%9},{%0,%1,%2,%3};"
        : "+f"(c[0]), "+f"(c[1]), "+f"(c[2]), "+f"(c[3])
        : "r"(a[0]), "r"(a[1]), "r"(a[2]), "r"(a[3]), "r"(b[0]), "r"(b[1]));
}

__device__ __forceinline__ uint32_t smem_u32(const void* p) {
    uint32_t a;
    asm("{ .reg .u64 t; cvta.to.shared.u64 t, %1; cvt.u32.u64 %0, t; }" : "=r"(a) : "l"(p));
    return a;
}
__device__ __forceinline__ void cpasync16(uint32_t dst, const void* src) {
    asm volatile("cp.async.cg.shared.global [%0], [%1], 16;" :: "r"(dst), "l"(src));
}
#define CP_COMMIT() asm volatile("cp.async.commit_group;")
#define CP_WAIT(n)  asm volatile("cp.async.wait_group %0;" :: "n"(n))

// ---------------- RNA tf32 round-copy (one-time weight prep) ----------------
__global__ void __launch_bounds__(256) k_round(float* __restrict__ dst,
                                               const float* __restrict__ src, int n4) {
    int i = blockIdx.x * 256 + threadIdx.x;
    if (i < n4) ((float4*)dst)[i] = tf32r4(((const float4*)src)[i]);
}

// ---------------- multi-stage cp.async tf32 GEMM ----------------
// C[m,n] = sum_k A[m,k] * (BT ? B[n,k] : B[k,n])  (+ bias[n] if BIAS)
// Inputs must be tf32-exact (pre-rounded): hardware RZ truncation is identity.
template <int BM, int BN, int BK, int WM, int WN, int STAGES,
          bool BT, bool BIAS, bool RNA, int MINCTA>
__global__ void __launch_bounds__(WM * WN * 32, MINCTA) gemm_cpa(
    const float* __restrict__ A, const float* __restrict__ B,
    float* __restrict__ C, const float* __restrict__ bias,
    int M, int N, int K)
{
    constexpr int THREADS = WM * WN * 32;
    constexpr int LA = BK + 8;
    constexpr int LB = BN + 8;
    constexpr int ASZ = BM * LA;
    constexpr int BSZE = BT ? BN * LA : BK * LB;
    constexpr int AITER = BM * BK / 4 / THREADS;
    constexpr int BITER = BN * BK / 4 / THREADS;

    extern __shared__ float sm[];

    const int tid  = threadIdx.x;
    const int lane = tid & 31;
    const int warp = tid >> 5;
    const int r  = lane >> 2;
    const int cq = lane & 3;
    const int wm = warp / WN, wn = warp % WN;
    constexpr int WTM = BM / WM, WTN = BN / WN;
    constexpr int MI = WTM / 16, NI = WTN / 8;
    const int mW = wm * WTM, nW = wn * WTN;
    const int m0 = blockIdx.y * BM;
    const int n0 = blockIdx.x * BN;

    float acc[MI][NI][4];
    #pragma unroll
    for (int mi = 0; mi < MI; mi++)
        #pragma unroll
        for (int ni = 0; ni < NI; ni++)
            #pragma unroll
            for (int j = 0; j < 4; j++) acc[mi][ni][j] = 0.0f;

    auto issue = [&](int k0, int buf) {
        float* As = sm + buf * (ASZ + BSZE);
        float* Bs = As + ASZ;
        uint32_t ab = smem_u32(As);
        uint32_t bb = smem_u32(Bs);
        #pragma unroll
        for (int i = 0; i < AITER; i++) {
            int idx = i * THREADS + tid;
            int row = idx / (BK / 4), k4 = idx % (BK / 4);
            cpasync16(ab + (row * LA + k4 * 4) * 4,
                      A + (long)(m0 + row) * K + k0 + k4 * 4);
        }
        if constexpr (BT) {
            #pragma unroll
            for (int i = 0; i < BITER; i++) {
                int idx = i * THREADS + tid;
                int row = idx / (BK / 4), k4 = idx % (BK / 4);
                cpasync16(bb + (row * LA + k4 * 4) * 4,
                          B + (long)(n0 + row) * K + k0 + k4 * 4);
            }
        } else {
            #pragma unroll
            for (int i = 0; i < BITER; i++) {
                int idx = i * THREADS + tid;
                int row = idx / (BN / 4), n4 = idx % (BN / 4);
                cpasync16(bb + (row * LB + n4 * 4) * 4,
                          B + (long)(k0 + row) * N + n0 + n4 * 4);
            }
        }
        CP_COMMIT();
    };
    auto compute = [&](int buf) {
        const float* As = sm + buf * (ASZ + BSZE);
        const float* Bs = As + ASZ;
        #pragma unroll
        for (int k8 = 0; k8 < BK / 8; k8++) {
            uint32_t af[MI][4], bf[NI][2];
            #pragma unroll
            for (int mi = 0; mi < MI; mi++) {
                int mr = mW + mi * 16 + r;
                af[mi][0] = f2u(As[mr * LA + k8 * 8 + cq]);
                af[mi][1] = f2u(As[(mr + 8) * LA + k8 * 8 + cq]);
                af[mi][2] = f2u(As[mr * LA + k8 * 8 + cq + 4]);
                af[mi][3] = f2u(As[(mr + 8) * LA + k8 * 8 + cq + 4]);
            }
            #pragma unroll
            for (int ni = 0; ni < NI; ni++) {
                int nc = nW + ni * 8 + r;
                if constexpr (BT) {
                    bf[ni][0] = f2u(Bs[nc * LA + k8 * 8 + cq]);
                    bf[ni][1] = f2u(Bs[nc * LA + k8 * 8 + cq + 4]);
                } else {
                    bf[ni][0] = f2u(Bs[(k8 * 8 + cq) * LB + nc]);
                    bf[ni][1] = f2u(Bs[(k8 * 8 + cq + 4) * LB + nc]);
                }
            }
            #pragma unroll
            for (int mi = 0; mi < MI; mi++)
                #pragma unroll
                for (int ni = 0; ni < NI; ni++)
                    mma8(acc[mi][ni], af[mi], bf[ni]);
        }
    };

    const int NTILES = K / BK;
    #pragma unroll
    for (int s = 0; s < STAGES - 1; s++) issue(s * BK, s);

    for (int t = 0; t < NTILES; t++) {
        if (t + STAGES - 1 < NTILES) {
            issue((t + STAGES - 1) * BK, (t + STAGES - 1) % STAGES);
            CP_WAIT(STAGES - 1);
        } else {
            int rem = NTILES - 1 - t;   // ≤ STAGES-2
            if constexpr (STAGES >= 4) { if (rem == 2) CP_WAIT(2); }
            if (rem == 1) CP_WAIT(1);
            else if (rem == 0) CP_WAIT(0);
        }
        __syncthreads();
        compute(t % STAGES);
        __syncthreads();
    }

    #pragma unroll
    for (int mi = 0; mi < MI; mi++) {
        int row = m0 + mW + mi * 16 + r;
        #pragma unroll
        for (int ni = 0; ni < NI; ni++) {
            int col = n0 + nW + ni * 8 + 2 * cq;
            float2 v0 = make_float2(acc[mi][ni][0], acc[mi][ni][1]);
            float2 v1 = make_float2(acc[mi][ni][2], acc[mi][ni][3]);
            if constexpr (BIAS) {
                float b0 = bias[col], b1 = bias[col + 1];
                v0.x += b0; v0.y += b1; v1.x += b0; v1.y += b1;
            }
            if constexpr (RNA) {
                v0.x = tf32r(v0.x); v0.y = tf32r(v0.y);
                v1.x = tf32r(v1.x); v1.y = tf32r(v1.y);
            }
            *(float2*)(C + (long)row * N + col) = v0;
            *(float2*)(C + (long)(row + 8) * N + col) = v1;
        }
    }
}

// ---------------- b2[e] = dot(Wo[e,:], bv) + bo[e]  (exact fp32) ----------------
__global__ void __launch_bounds__(256) k_b2(const float* __restrict__ Wo,
                                            const float* __restrict__ bv,
                                            const float* __restrict__ bo) {
    int e = blockIdx.x * 256 + threadIdx.x;
    const float4* wo = (const float4*)(Wo + (long)e * HIDDEN);
    const float4* bvv = (const float4*)bv;
    float acc = 0.0f;
    #pragma unroll 4
    for (int i = 0; i < HIDDEN / 4; i++) {
        float4 a = wo[i], b = bvv[i];
        acc = fmaf(a.x, b.x, acc); acc = fmaf(a.y, b.y, acc);
        acc = fmaf(a.z, b.z, acc); acc = fmaf(a.w, b.w, acc);
    }
    g_b2[e] = acc + bo[e];
}

// ---------------- fused attention: persistent CTAs, flattened cp.async pipeline ----------------
#define LQ2 1032
#define OFF_X  0
#define OFF_SP (3 * TT * LQ2)
#define OFF_P  (OFF_SP + 16 * 16 * TT)
#define OFF_M  (OFF_P + 16 * 24)
#define OFF_L  (OFF_M + 16)
#define OFF_SC (OFF_L + 16)
#define OFF_LG (OFF_SC + 16)
#define FUSED_SMEM ((OFF_LG + SEGLEN) * 4)
#define FGRID 148

__global__ void __launch_bounds__(512, 1) fused_attn(
    const float* __restrict__ X, const float* __restrict__ logits,
    float* __restrict__ Y)
{
    extern __shared__ float sm[];
    float* Xs  = sm + OFF_X;
    float* Sp  = sm + OFF_SP;
    float* Ps  = sm + OFF_P;
    float* mS  = sm + OFF_M;
    float* lS  = sm + OFF_L;
    float* scS = sm + OFF_SC;
    float* lgS = sm + OFF_LG;

    const int tid  = threadIdx.x;
    const int lane = tid & 31;
    const int w    = tid >> 5;        // 0..15, d-chunk = [w*64, w*64+64)
    const int r    = lane >> 2;
    const int cq   = lane & 3;

    // segments handled by this CTA: b = blockIdx.x + i*FGRID (while < BSZ)
    const int nb = (BSZ - blockIdx.x + FGRID - 1) / FGRID;   // 4 or 3
    const int NT = SEGLEN / TT;                               // 16
    const int NG = nb * NT;

    auto issueG = [&](int g) {
        int bcur = blockIdx.x + (g >> 4) * FGRID;
        int it   = g & 15;
        const float* src0 = X + (long)bcur * SEGLEN * HIDDEN + (long)it * TT * HIDDEN;
        uint32_t dstb = smem_u32(Xs + (g % 3) * TT * LQ2);
        #pragma unroll
        for (int i = 0; i < 8; i++) {
            int idx = i * 512 + tid;          // 4096 float4 per stage
            int row = idx >> 8, c4 = idx & 255;
            cpasync16(dstb + (row * LQ2 + c4 * 4) * 4, src0 + row * HIDDEN + c4 * 4);
        }
        CP_COMMIT();
    };
    issueG(0); issueG(1);

    // Q2 fragments in registers (Q2 is RNA-rounded tf32-exact); shared across segments
    uint32_t afq[8][4];
    #pragma unroll
    for (int k8 = 0; k8 < 8; k8++) {
        int col = w * 64 + k8 * 8 + cq;
        afq[k8][0] = f2u(__ldg(&g_q2[(long)r * HIDDEN + col]));
        afq[k8][1] = f2u(__ldg(&g_q2[(long)(r + 8) * HIDDEN + col]));
        afq[k8][2] = f2u(__ldg(&g_q2[(long)r * HIDDEN + col + 4]));
        afq[k8][3] = f2u(__ldg(&g_q2[(long)(r + 8) * HIDDEN + col + 4]));
    }

    float acc[8][4];
    #pragma unroll
    for (int ni = 0; ni < 8; ni++)
        #pragma unroll
        for (int j = 0; j < 4; j++) acc[ni][j] = 0.0f;

    __syncthreads();   // not strictly needed before first tile state-set, but cheap & safe

    for (int g = 0; g < NG; g++) {
        const int it   = g & 15;
        const int bcur = blockIdx.x + (g >> 4) * FGRID;

        if (g + 2 < NG) { issueG(g + 2); CP_WAIT(2); }
        else if (NG - 1 - g == 1) CP_WAIT(1);
        else CP_WAIT(0);
        __syncthreads();
        const float* Xt = Xs + (g % 3) * TT * LQ2;

        // ---- segment start: load logits, reset online-softmax state ----
        // (read by softmax phase, which is after the next __syncthreads)
        if (it == 0) {
            if (tid < 256) lgS[tid] = logits[(long)bcur * SEGLEN + tid];
            if (tid < 16) { mS[tid] = -INFINITY; lS[tid] = 0.0f; }
            // acc self-resets: first-tile scale = exp(-inf) = 0
        }

        // ---- scores: warp covers d in [w*64, w*64+64) ----
        {
            float sacc[2][4] = {{0,0,0,0},{0,0,0,0}};
            #pragma unroll
            for (int k8 = 0; k8 < 8; k8++) {
                int kk = w * 64 + k8 * 8;
                uint32_t bf[2][2];
                #pragma unroll
                for (int nt = 0; nt < 2; nt++) {
                    int nc = nt * 8 + r;
                    bf[nt][0] = f2u(Xt[nc * LQ2 + kk + cq]);
                    bf[nt][1] = f2u(Xt[nc * LQ2 + kk + cq + 4]);
                }
                mma8(sacc[0], afq[k8], bf[0]);
                mma8(sacc[1], afq[k8], bf[1]);
            }
            #pragma unroll
            for (int nt = 0; nt < 2; nt++) {
                int c0 = nt * 8 + 2 * cq;
                Sp[(w * 16 + r) * TT + c0]         = sacc[nt][0];
                Sp[(w * 16 + r) * TT + c0 + 1]     = sacc[nt][1];
                Sp[(w * 16 + r + 8) * TT + c0]     = sacc[nt][2];
                Sp[(w * 16 + r + 8) * TT + c0 + 1] = sacc[nt][3];
            }
        }
        __syncthreads();

        // ---- online softmax: thread (s = tid>>4, t = tid&15), tid < 256 ----
        if (tid < 256) {
            int s = tid >> 4, t = tid & 15;
            float accs = 0.0f;
            #pragma unroll
            for (int ww = 0; ww < 16; ww++) accs += Sp[(ww * 16 + s) * TT + t];
            float v = accs * SCALE + lgS[it * TT + t];
            float m_t = v;
            #pragma unroll
            for (int o = 8; o; o >>= 1) m_t = fmaxf(m_t, __shfl_xor_sync(0xffffffffu, m_t, o));
            float m_old = mS[s];
            float newm = fmaxf(m_old, m_t);
            float p = expf(v - newm);
            Ps[s * 24 + t] = tf32r(p);
            float sum = p;
            #pragma unroll
            for (int o = 8; o; o >>= 1) sum += __shfl_xor_sync(0xffffffffu, sum, o);
            if (t == 0) {
                float scale = expf(m_old - newm); // 0 on first tile of segment
                lS[s] = lS[s] * scale + sum;
                mS[s] = newm;
                scS[s] = scale;
            }
        }
        __syncthreads();

        // ---- rescale Y acc, then Y += P @ X_tile ----
        {
            float sc0 = scS[r], sc1 = scS[r + 8];
            #pragma unroll
            for (int ni = 0; ni < 8; ni++) {
                acc[ni][0] *= sc0; acc[ni][1] *= sc0;
                acc[ni][2] *= sc1; acc[ni][3] *= sc1;
            }
            #pragma unroll
            for (int k8 = 0; k8 < 2; k8++) {
                uint32_t af[4];
                af[0] = f2u(Ps[r * 24 + k8 * 8 + cq]);
                af[1] = f2u(Ps[(r + 8) * 24 + k8 * 8 + cq]);
                af[2] = f2u(Ps[r * 24 + k8 * 8 + cq + 4]);
                af[3] = f2u(Ps[(r + 8) * 24 + k8 * 8 + cq + 4]);
                #pragma unroll
                for (int ni = 0; ni < 8; ni++) {
                    int nc = w * 64 + ni * 8 + r;
                    uint32_t bf[2];
                    bf[0] = f2u(Xt[(k8 * 8 + cq) * LQ2 + nc]);
                    bf[1] = f2u(Xt[(k8 * 8 + cq + 4) * LQ2 + nc]);
                    mma8(acc[ni], af, bf);
                }
            }
        }

        // ---- segment end: write Y (lS stable since softmax barrier) ----
        if (it == 15) {
            float inv0 = 1.0f / lS[r];
            float inv1 = 1.0f / lS[r + 8];
            float* Y0 = Y + ((long)bcur * SLOTS + r) * HIDDEN;
            float* Y1 = Y + ((long)bcur * SLOTS + r + 8) * HIDDEN;
            #pragma unroll
            for (int ni = 0; ni < 8; ni++) {
                int col = w * 64 + ni * 8 + 2 * cq;
                *(float2*)(Y0 + col) = make_float2(tf32r(acc[ni][0] * inv0), tf32r(acc[ni][1] * inv0));
                *(float2*)(Y1 + col) = make_float2(tf32r(acc[ni][2] * inv1), tf32r(acc[ni][3] * inv1));
            }
        }
        __syncthreads();   // protect Xs buffer + Ps/scS/mS/lS before next tile
    }
}

// ---------------- launch ----------------
extern "C" void kernel_launch(void* const* d_in, const int* in_sizes, int n_in,
                              void* d_out, int out_size) {
    const float* X      = (const float*)d_in[0];   // [512,256,1024]
    const float* logits = (const float*)d_in[1];   // [512,256]
    const float* LQ     = (const float*)d_in[2];   // [16,1024]
    const float* Wq     = (const float*)d_in[3];
    const float* bq     = (const float*)d_in[4];
    const float* Wk     = (const float*)d_in[5];
    // d_in[6] = bk: cancels in softmax, unused
    const float* Wv     = (const float*)d_in[7];
    const float* bv     = (const float*)d_in[8];
    const float* Wo     = (const float*)d_in[9];
    const float* bo     = (const float*)d_in[10];
    float* out = (float*)d_out;

    float *lqp, *wqp, *wkp, *wop, *wvp, *q1p, *q2p, *w2p, *b2p, *yp;
    cudaGetSymbolAddress((void**)&lqp, g_lq);
    cudaGetSymbolAddress((void**)&wqp, g_wq);
    cudaGetSymbolAddress((void**)&wkp, g_wk);
    cudaGetSymbolAddress((void**)&wop, g_wo);
    cudaGetSymbolAddress((void**)&wvp, g_wv);
    cudaGetSymbolAddress((void**)&q1p, g_q1);
    cudaGetSymbolAddress((void**)&q2p, g_q2);
    cudaGetSymbolAddress((void**)&w2p, g_w2);
    cudaGetSymbolAddress((void**)&b2p, g_b2);
    cudaGetSymbolAddress((void**)&yp,  g_y);

    // smem opt-in (idempotent)
    cudaFuncSetAttribute((const void*)gemm_cpa<16,64,32,1,4,4,true,true,true,1>,
                         cudaFuncAttributeMaxDynamicSharedMemorySize, 51200);
    cudaFuncSetAttribute((const void*)gemm_cpa<16,64,32,1,4,4,false,false,true,1>,
                         cudaFuncAttributeMaxDynamicSharedMemorySize, 47104);
    cudaFuncSetAttribute((const void*)gemm_cpa<64,64,32,2,2,3,false,false,true,1>,
                         cudaFuncAttributeMaxDynamicSharedMemorySize, 58368);
    cudaFuncSetAttribute((const void*)gemm_cpa<128,128,32,2,2,2,true,true,false,2>,
                         cudaFuncAttributeMaxDynamicSharedMemorySize, 81920);
    cudaFuncSetAttribute((const void*)fused_attn,
                         cudaFuncAttributeMaxDynamicSharedMemorySize, FUSED_SMEM);

    // 0) one-time RNA rounding of weights (tf32-exact inputs -> RZ identity in GEMMs)
    const int W4 = HIDDEN * HIDDEN / 4;
    k_round<<<W4 / 256, 256>>>(wqp, Wq, W4);
    k_round<<<W4 / 256, 256>>>(wkp, Wk, W4);
    k_round<<<W4 / 256, 256>>>(wop, Wo, W4);
    k_round<<<W4 / 256, 256>>>(wvp, Wv, W4);
    k_round<<<SLOTS * HIDDEN / 4 / 256 + 1, 256>>>(lqp, LQ, SLOTS * HIDDEN / 4);

    // 1) q1 = LQ @ Wq^T + bq    [16,1024]
    gemm_cpa<16, 64, 32, 1, 4, 4, true, true, true, 1><<<dim3(16, 1), 128, 51200>>>(
        lqp, wqp, q1p, bq, 16, 1024, 1024);
    // 2) Q2 = q1 @ Wk           [16,1024]
    gemm_cpa<16, 64, 32, 1, 4, 4, false, false, true, 1><<<dim3(16, 1), 128, 47104>>>(
        q1p, wkp, q2p, nullptr, 16, 1024, 1024);
    // 3) b2 = Wo @ bv + bo      (exact fp32, raw weights)
    k_b2<<<4, 256>>>(Wo, bv, bo);
    // 4) W2 = Wo @ Wv           [1024,1024]
    gemm_cpa<64, 64, 32, 2, 2, 3, false, false, true, 1><<<dim3(16, 16), 128, 58368>>>(
        wop, wvp, w2p, nullptr, 1024, 1024, 1024);
    // 5) fused attention (persistent): Y[b] = softmax(Q2·X^T/32 + logits) @ X
    fused_attn<<<FGRID, 512, FUSED_SMEM>>>(X, logits, yp);
    // 6) out = Y @ W2^T + b2    [8192,1024] (inputs tf32-exact)
    gemm_cpa<128, 128, 32, 2, 2, 2, true, true, false, 2><<<dim3(8, 64), 128, 81920>>>(
        yp, w2p, out, b2p, BSZ * SLOTS, HIDDEN, HIDDEN);
}

// round 10
// speedup vs baseline: 1.3463x; 1.1851x over previous
#include <cuda_runtime.h>
#include <cuda_fp16.h>
#include <cstdint>

#define HIDDEN 1024
#define SLOTS 16
#define BSZ 512
#define SEGLEN 256
#define TT 16            // t-tile in fused attention
#define SCALE 0.03125f   // 1/sqrt(1024)

// ---------------- scratch (device globals; no allocation) ----------------
__device__ float  g_lq[SLOTS * HIDDEN];                   // RNA-rounded latent queries
__device__ float  g_wq[HIDDEN * HIDDEN];                  // RNA-rounded weights
__device__ float  g_wk[HIDDEN * HIDDEN];
__device__ float  g_wo[HIDDEN * HIDDEN];
__device__ float  g_wv[HIDDEN * HIDDEN];
__device__ float  g_q1[SLOTS * HIDDEN];
__device__ float  g_q2[SLOTS * HIDDEN];
__device__ __half g_w2h[HIDDEN * HIDDEN];                 // fp16 W2 = Wo@Wv
__device__ float  g_b2[HIDDEN];
__device__ __half g_yh[(size_t)BSZ * SLOTS * HIDDEN];     // fp16 Y [b][s][d]

// ---------------- helpers ----------------
__device__ __forceinline__ float tf32r(float x) {
    uint32_t u;
    asm("cvt.rna.tf32.f32 %0, %1;" : "=r"(u) : "f"(x));
    return __uint_as_float(u);
}
__device__ __forceinline__ float4 tf32r4(float4 v) {
    return make_float4(tf32r(v.x), tf32r(v.y), tf32r(v.z), tf32r(v.w));
}
__device__ __forceinline__ uint32_t f2u(float x) { return __float_as_uint(x); }

__device__ __forceinline__ void mma8(float* c, const uint32_t* a, const uint32_t* b) {
    asm volatile(
        "mma.sync.aligned.m16n8k8.row.col.f32.tf32.tf32.f32 "
        "{%0,%1,%2,%3},{%4,%5,%6,%7},{%8,%9},{%0,%1,%2,%3};"
        : "+f"(c[0]), "+f"(c[1]), "+f"(c[2]), "+f"(c[3])
        : "r"(a[0]), "r"(a[1]), "r"(a[2]), "r"(a[3]), "r"(b[0]), "r"(b[1]));
}
__device__ __forceinline__ void mma16h(float* c, const uint32_t* a, const uint32_t* b) {
    asm volatile(
        "mma.sync.aligned.m16n8k16.row.col.f32.f16.f16.f32 "
        "{%0,%1,%2,%3},{%4,%5,%6,%7},{%8,%9},{%0,%1,%2,%3};"
        : "+f"(c[0]), "+f"(c[1]), "+f"(c[2]), "+f"(c[3])
        : "r"(a[0]), "r"(a[1]), "r"(a[2]), "r"(a[3]), "r"(b[0]), "r"(b[1]));
}

__device__ __forceinline__ uint32_t smem_u32(const void* p) {
    uint32_t a;
    asm("{ .reg .u64 t; cvta.to.shared.u64 t, %1; cvt.u32.u64 %0, t; }" : "=r"(a) : "l"(p));
    return a;
}
__device__ __forceinline__ void cpasync16(uint32_t dst, const void* src) {
    asm volatile("cp.async.cg.shared.global [%0], [%1], 16;" :: "r"(dst), "l"(src));
}
#define CP_COMMIT() asm volatile("cp.async.commit_group;")
#define CP_WAIT(n)  asm volatile("cp.async.wait_group %0;" :: "n"(n))

// ---------------- batched RNA round-copy: 4 weight matrices in one launch ----------------
__global__ void __launch_bounds__(256) k_round4(
    float* d0, const float* s0, float* d1, const float* s1,
    float* d2, const float* s2, float* d3, const float* s3) {
    const float* s; float* d;
    switch (blockIdx.y) {
        case 0: s = s0; d = d0; break;
        case 1: s = s1; d = d1; break;
        case 2: s = s2; d = d2; break;
        default: s = s3; d = d3; break;
    }
    int i = blockIdx.x * 256 + threadIdx.x;   // 262144 float4 per matrix
    ((float4*)d)[i] = tf32r4(((const float4*)s)[i]);
}
__global__ void __launch_bounds__(256) k_round(float* __restrict__ dst,
                                               const float* __restrict__ src, int n4) {
    int i = blockIdx.x * 256 + threadIdx.x;
    if (i < n4) ((float4*)dst)[i] = tf32r4(((const float4*)src)[i]);
}

// ---------------- multi-stage cp.async tf32 GEMM ----------------
// C[m,n] = sum_k A[m,k] * (BT ? B[n,k] : B[k,n])  (+ bias[n] if BIAS)
// Inputs must be tf32-exact (pre-rounded): hardware RZ truncation is identity.
// HOUT: store C as __half (RNE); else fp32 (optionally RNA-rounded).
template <int BM, int BN, int BK, int WM, int WN, int STAGES,
          bool BT, bool BIAS, bool RNA, bool HOUT, int MINCTA>
__global__ void __launch_bounds__(WM * WN * 32, MINCTA) gemm_cpa(
    const float* __restrict__ A, const float* __restrict__ B,
    float* __restrict__ C, const float* __restrict__ bias,
    int M, int N, int K)
{
    constexpr int THREADS = WM * WN * 32;
    constexpr int LA = BK + 8;
    constexpr int LB = BN + 8;
    constexpr int ASZ = BM * LA;
    constexpr int BSZE = BT ? BN * LA : BK * LB;
    constexpr int AITER = BM * BK / 4 / THREADS;
    constexpr int BITER = BN * BK / 4 / THREADS;

    extern __shared__ float sm[];

    const int tid  = threadIdx.x;
    const int lane = tid & 31;
    const int warp = tid >> 5;
    const int r  = lane >> 2;
    const int cq = lane & 3;
    const int wm = warp / WN, wn = warp % WN;
    constexpr int WTM = BM / WM, WTN = BN / WN;
    constexpr int MI = WTM / 16, NI = WTN / 8;
    const int mW = wm * WTM, nW = wn * WTN;
    const int m0 = blockIdx.y * BM;
    const int n0 = blockIdx.x * BN;

    float acc[MI][NI][4];
    #pragma unroll
    for (int mi = 0; mi < MI; mi++)
        #pragma unroll
        for (int ni = 0; ni < NI; ni++)
            #pragma unroll
            for (int j = 0; j < 4; j++) acc[mi][ni][j] = 0.0f;

    auto issue = [&](int k0, int buf) {
        float* As = sm + buf * (ASZ + BSZE);
        float* Bs = As + ASZ;
        uint32_t ab = smem_u32(As);
        uint32_t bb = smem_u32(Bs);
        #pragma unroll
        for (int i = 0; i < AITER; i++) {
            int idx = i * THREADS + tid;
            int row = idx / (BK / 4), k4 = idx % (BK / 4);
            cpasync16(ab + (row * LA + k4 * 4) * 4,
                      A + (long)(m0 + row) * K + k0 + k4 * 4);
        }
        if constexpr (BT) {
            #pragma unroll
            for (int i = 0; i < BITER; i++) {
                int idx = i * THREADS + tid;
                int row = idx / (BK / 4), k4 = idx % (BK / 4);
                cpasync16(bb + (row * LA + k4 * 4) * 4,
                          B + (long)(n0 + row) * K + k0 + k4 * 4);
            }
        } else {
            #pragma unroll
            for (int i = 0; i < BITER; i++) {
                int idx = i * THREADS + tid;
                int row = idx / (BN / 4), n4 = idx % (BN / 4);
                cpasync16(bb + (row * LB + n4 * 4) * 4,
                          B + (long)(k0 + row) * N + n0 + n4 * 4);
            }
        }
        CP_COMMIT();
    };
    auto compute = [&](int buf) {
        const float* As = sm + buf * (ASZ + BSZE);
        const float* Bs = As + ASZ;
        #pragma unroll
        for (int k8 = 0; k8 < BK / 8; k8++) {
            uint32_t af[MI][4], bf[NI][2];
            #pragma unroll
            for (int mi = 0; mi < MI; mi++) {
                int mr = mW + mi * 16 + r;
                af[mi][0] = f2u(As[mr * LA + k8 * 8 + cq]);
                af[mi][1] = f2u(As[(mr + 8) * LA + k8 * 8 + cq]);
                af[mi][2] = f2u(As[mr * LA + k8 * 8 + cq + 4]);
                af[mi][3] = f2u(As[(mr + 8) * LA + k8 * 8 + cq + 4]);
            }
            #pragma unroll
            for (int ni = 0; ni < NI; ni++) {
                int nc = nW + ni * 8 + r;
                if constexpr (BT) {
                    bf[ni][0] = f2u(Bs[nc * LA + k8 * 8 + cq]);
                    bf[ni][1] = f2u(Bs[nc * LA + k8 * 8 + cq + 4]);
                } else {
                    bf[ni][0] = f2u(Bs[(k8 * 8 + cq) * LB + nc]);
                    bf[ni][1] = f2u(Bs[(k8 * 8 + cq + 4) * LB + nc]);
                }
            }
            #pragma unroll
            for (int mi = 0; mi < MI; mi++)
                #pragma unroll
                for (int ni = 0; ni < NI; ni++)
                    mma8(acc[mi][ni], af[mi], bf[ni]);
        }
    };

    const int NTILES = K / BK;
    #pragma unroll
    for (int s = 0; s < STAGES - 1; s++) issue(s * BK, s);

    for (int t = 0; t < NTILES; t++) {
        if (t + STAGES - 1 < NTILES) {
            issue((t + STAGES - 1) * BK, (t + STAGES - 1) % STAGES);
            CP_WAIT(STAGES - 1);
        } else {
            int rem = NTILES - 1 - t;   // ≤ STAGES-2
            if constexpr (STAGES >= 4) { if (rem == 2) CP_WAIT(2); }
            if (rem == 1) CP_WAIT(1);
            else if (rem == 0) CP_WAIT(0);
        }
        __syncthreads();
        compute(t % STAGES);
        __syncthreads();
    }

    #pragma unroll
    for (int mi = 0; mi < MI; mi++) {
        int row = m0 + mW + mi * 16 + r;
        #pragma unroll
        for (int ni = 0; ni < NI; ni++) {
            int col = n0 + nW + ni * 8 + 2 * cq;
            float2 v0 = make_float2(acc[mi][ni][0], acc[mi][ni][1]);
            float2 v1 = make_float2(acc[mi][ni][2], acc[mi][ni][3]);
            if constexpr (BIAS) {
                float b0 = bias[col], b1 = bias[col + 1];
                v0.x += b0; v0.y += b1; v1.x += b0; v1.y += b1;
            }
            if constexpr (HOUT) {
                __half* Ch = (__half*)C;
                *(__half2*)(Ch + (long)row * N + col)       = __floats2half2_rn(v0.x, v0.y);
                *(__half2*)(Ch + (long)(row + 8) * N + col) = __floats2half2_rn(v1.x, v1.y);
            } else {
                if constexpr (RNA) {
                    v0.x = tf32r(v0.x); v0.y = tf32r(v0.y);
                    v1.x = tf32r(v1.x); v1.y = tf32r(v1.y);
                }
                *(float2*)(C + (long)row * N + col) = v0;
                *(float2*)(C + (long)(row + 8) * N + col) = v1;
            }
        }
    }
}

// ---------------- fp16 GEMM for the final projection ----------------
// C[m,n] = sum_k A[m,k] * B[n,k] + bias[n];  A,B half, C fp32.
// BM=BN=128, BK=64, 128 threads (4 warps, 2x2), MI=4, NI=8, 2-stage cp.async.
#define HBM 128
#define HBN 128
#define HBK 64
#define HLA 72            // halves per row (BK + 8 pad)
#define HSTG ((HBM + HBN) * HLA)   // halves per stage = 18432 (36864 B)

__global__ void __launch_bounds__(128, 2) gemm_h(
    const __half* __restrict__ A, const __half* __restrict__ B,
    float* __restrict__ C, const float* __restrict__ bias,
    int M, int N, int K)
{
    extern __shared__ __half smh[];

    const int tid  = threadIdx.x;
    const int lane = tid & 31;
    const int warp = tid >> 5;
    const int r  = lane >> 2;
    const int cq = lane & 3;
    const int wm = warp >> 1, wn = warp & 1;
    const int mW = wm * 64, nW = wn * 64;
    const int m0 = blockIdx.y * HBM;
    const int n0 = blockIdx.x * HBN;

    float acc[4][8][4];
    #pragma unroll
    for (int mi = 0; mi < 4; mi++)
        #pragma unroll
        for (int ni = 0; ni < 8; ni++)
            #pragma unroll
            for (int j = 0; j < 4; j++) acc[mi][ni][j] = 0.0f;

    auto issue = [&](int k0, int buf) {
        __half* As = smh + buf * HSTG;
        __half* Bs = As + HBM * HLA;
        uint32_t ab = smem_u32(As);
        uint32_t bb = smem_u32(Bs);
        #pragma unroll
        for (int i = 0; i < 8; i++) {            // 128*64/8/128 = 8
            int idx = i * 128 + tid;
            int row = idx >> 3, c8 = idx & 7;
            cpasync16(ab + (row * HLA + c8 * 8) * 2,
                      A + (long)(m0 + row) * K + k0 + c8 * 8);
        }
        #pragma unroll
        for (int i = 0; i < 8; i++) {
            int idx = i * 128 + tid;
            int row = idx >> 3, c8 = idx & 7;
            cpasync16(bb + (row * HLA + c8 * 8) * 2,
                      B + (long)(n0 + row) * K + k0 + c8 * 8);
        }
        CP_COMMIT();
    };
    auto compute = [&](int buf) {
        const __half* As = smh + buf * HSTG;
        const __half* Bs = As + HBM * HLA;
        #pragma unroll
        for (int k16 = 0; k16 < 4; k16++) {
            uint32_t af[4][4], bf[8][2];
            #pragma unroll
            for (int mi = 0; mi < 4; mi++) {
                int mr = mW + mi * 16 + r;
                const __half* p0 = As + mr * HLA + k16 * 16 + 2 * cq;
                const __half* p1 = As + (mr + 8) * HLA + k16 * 16 + 2 * cq;
                af[mi][0] = *(const uint32_t*)p0;
                af[mi][1] = *(const uint32_t*)p1;
                af[mi][2] = *(const uint32_t*)(p0 + 8);
                af[mi][3] = *(const uint32_t*)(p1 + 8);
            }
            #pragma unroll
            for (int ni = 0; ni < 8; ni++) {
                int nc = nW + ni * 8 + r;
                const __half* p = Bs + nc * HLA + k16 * 16 + 2 * cq;
                bf[ni][0] = *(const uint32_t*)p;
                bf[ni][1] = *(const uint32_t*)(p + 8);
            }
            #pragma unroll
            for (int mi = 0; mi < 4; mi++)
                #pragma unroll
                for (int ni = 0; ni < 8; ni++)
                    mma16h(acc[mi][ni], af[mi], bf[ni]);
        }
    };

    const int NTILES = K / HBK;   // 16
    issue(0, 0);
    for (int t = 0; t < NTILES; t++) {
        if (t + 1 < NTILES) { issue((t + 1) * HBK, (t + 1) & 1); CP_WAIT(1); }
        else CP_WAIT(0);
        __syncthreads();
        compute(t & 1);
        __syncthreads();
    }

    #pragma unroll
    for (int mi = 0; mi < 4; mi++) {
        int row = m0 + mW + mi * 16 + r;
        #pragma unroll
        for (int ni = 0; ni < 8; ni++) {
            int col = n0 + nW + ni * 8 + 2 * cq;
            float b0 = bias[col], b1 = bias[col + 1];
            *(float2*)(C + (long)row * N + col) =
                make_float2(acc[mi][ni][0] + b0, acc[mi][ni][1] + b1);
            *(float2*)(C + (long)(row + 8) * N + col) =
                make_float2(acc[mi][ni][2] + b0, acc[mi][ni][3] + b1);
        }
    }
}

// ---------------- b2[e] = dot(Wo[e,:], bv) + bo[e]  (exact fp32) ----------------
__global__ void __launch_bounds__(256) k_b2(const float* __restrict__ Wo,
                                            const float* __restrict__ bv,
                                            const float* __restrict__ bo) {
    int e = blockIdx.x * 256 + threadIdx.x;
    const float4* wo = (const float4*)(Wo + (long)e * HIDDEN);
    const float4* bvv = (const float4*)bv;
    float acc = 0.0f;
    #pragma unroll 4
    for (int i = 0; i < HIDDEN / 4; i++) {
        float4 a = wo[i], b = bvv[i];
        acc = fmaf(a.x, b.x, acc); acc = fmaf(a.y, b.y, acc);
        acc = fmaf(a.z, b.z, acc); acc = fmaf(a.w, b.w, acc);
    }
    g_b2[e] = acc + bo[e];
}

// ---------------- fused attention: persistent CTAs, flattened cp.async pipeline ----------------
#define LQ2 1032
#define OFF_X  0
#define OFF_SP (3 * TT * LQ2)
#define OFF_P  (OFF_SP + 16 * 16 * TT)
#define OFF_M  (OFF_P + 16 * 24)
#define OFF_L  (OFF_M + 16)
#define OFF_SC (OFF_L + 16)
#define OFF_LG (OFF_SC + 16)
#define FUSED_SMEM ((OFF_LG + SEGLEN) * 4)
#define FGRID 148

__global__ void __launch_bounds__(512, 1) fused_attn(
    const float* __restrict__ X, const float* __restrict__ logits,
    __half* __restrict__ Y)
{
    extern __shared__ float sm[];
    float* Xs  = sm + OFF_X;
    float* Sp  = sm + OFF_SP;
    float* Ps  = sm + OFF_P;
    float* mS  = sm + OFF_M;
    float* lS  = sm + OFF_L;
    float* scS = sm + OFF_SC;
    float* lgS = sm + OFF_LG;

    const int tid  = threadIdx.x;
    const int lane = tid & 31;
    const int w    = tid >> 5;        // 0..15, d-chunk = [w*64, w*64+64)
    const int r    = lane >> 2;
    const int cq   = lane & 3;

    const int nb = (BSZ - blockIdx.x + FGRID - 1) / FGRID;   // 4 or 3
    const int NT = SEGLEN / TT;                               // 16
    const int NG = nb * NT;

    auto issueG = [&](int g) {
        int bcur = blockIdx.x + (g >> 4) * FGRID;
        int it   = g & 15;
        const float* src0 = X + (long)bcur * SEGLEN * HIDDEN + (long)it * TT * HIDDEN;
        uint32_t dstb = smem_u32(Xs + (g % 3) * TT * LQ2);
        #pragma unroll
        for (int i = 0; i < 8; i++) {
            int idx = i * 512 + tid;          // 4096 float4 per stage
            int row = idx >> 8, c4 = idx & 255;
            cpasync16(dstb + (row * LQ2 + c4 * 4) * 4, src0 + row * HIDDEN + c4 * 4);
        }
        CP_COMMIT();
    };
    issueG(0); issueG(1);

    // Q2 fragments in registers (Q2 is RNA-rounded tf32-exact); shared across segments
    uint32_t afq[8][4];
    #pragma unroll
    for (int k8 = 0; k8 < 8; k8++) {
        int col = w * 64 + k8 * 8 + cq;
        afq[k8][0] = f2u(__ldg(&g_q2[(long)r * HIDDEN + col]));
        afq[k8][1] = f2u(__ldg(&g_q2[(long)(r + 8) * HIDDEN + col]));
        afq[k8][2] = f2u(__ldg(&g_q2[(long)r * HIDDEN + col + 4]));
        afq[k8][3] = f2u(__ldg(&g_q2[(long)(r + 8) * HIDDEN + col + 4]));
    }

    float acc[8][4];
    #pragma unroll
    for (int ni = 0; ni < 8; ni++)
        #pragma unroll
        for (int j = 0; j < 4; j++) acc[ni][j] = 0.0f;

    __syncthreads();

    for (int g = 0; g < NG; g++) {
        const int it   = g & 15;
        const int bcur = blockIdx.x + (g >> 4) * FGRID;

        if (g + 2 < NG) { issueG(g + 2); CP_WAIT(2); }
        else if (NG - 1 - g == 1) CP_WAIT(1);
        else CP_WAIT(0);
        __syncthreads();
        const float* Xt = Xs + (g % 3) * TT * LQ2;

        if (it == 0) {
            if (tid < 256) lgS[tid] = logits[(long)bcur * SEGLEN + tid];
            if (tid < 16) { mS[tid] = -INFINITY; lS[tid] = 0.0f; }
        }

        // ---- scores: warp covers d in [w*64, w*64+64) ----
        {
            float sacc[2][4] = {{0,0,0,0},{0,0,0,0}};
            #pragma unroll
            for (int k8 = 0; k8 < 8; k8++) {
                int kk = w * 64 + k8 * 8;
                uint32_t bf[2][2];
                #pragma unroll
                for (int nt = 0; nt < 2; nt++) {
                    int nc = nt * 8 + r;
                    bf[nt][0] = f2u(Xt[nc * LQ2 + kk + cq]);
                    bf[nt][1] = f2u(Xt[nc * LQ2 + kk + cq + 4]);
                }
                mma8(sacc[0], afq[k8], bf[0]);
                mma8(sacc[1], afq[k8], bf[1]);
            }
            #pragma unroll
            for (int nt = 0; nt < 2; nt++) {
                int c0 = nt * 8 + 2 * cq;
                Sp[(w * 16 + r) * TT + c0]         = sacc[nt][0];
                Sp[(w * 16 + r) * TT + c0 + 1]     = sacc[nt][1];
                Sp[(w * 16 + r + 8) * TT + c0]     = sacc[nt][2];
                Sp[(w * 16 + r + 8) * TT + c0 + 1] = sacc[nt][3];
            }
        }
        __syncthreads();

        // ---- online softmax: thread (s = tid>>4, t = tid&15), tid < 256 ----
        if (tid < 256) {
            int s = tid >> 4, t = tid & 15;
            float accs = 0.0f;
            #pragma unroll
            for (int ww = 0; ww < 16; ww++) accs += Sp[(ww * 16 + s) * TT + t];
            float v = accs * SCALE + lgS[it * TT + t];
            float m_t = v;
            #pragma unroll
            for (int o = 8; o; o >>= 1) m_t = fmaxf(m_t, __shfl_xor_sync(0xffffffffu, m_t, o));
            float m_old = mS[s];
            float newm = fmaxf(m_old, m_t);
            float p = expf(v - newm);
            Ps[s * 24 + t] = tf32r(p);
            float sum = p;
            #pragma unroll
            for (int o = 8; o; o >>= 1) sum += __shfl_xor_sync(0xffffffffu, sum, o);
            if (t == 0) {
                float scale = expf(m_old - newm); // 0 on first tile of segment
                lS[s] = lS[s] * scale + sum;
                mS[s] = newm;
                scS[s] = scale;
            }
        }
        __syncthreads();

        // ---- rescale Y acc, then Y += P @ X_tile ----
        {
            float sc0 = scS[r], sc1 = scS[r + 8];
            #pragma unroll
            for (int ni = 0; ni < 8; ni++) {
                acc[ni][0] *= sc0; acc[ni][1] *= sc0;
                acc[ni][2] *= sc1; acc[ni][3] *= sc1;
            }
            #pragma unroll
            for (int k8 = 0; k8 < 2; k8++) {
                uint32_t af[4];
                af[0] = f2u(Ps[r * 24 + k8 * 8 + cq]);
                af[1] = f2u(Ps[(r + 8) * 24 + k8 * 8 + cq]);
                af[2] = f2u(Ps[r * 24 + k8 * 8 + cq + 4]);
                af[3] = f2u(Ps[(r + 8) * 24 + k8 * 8 + cq + 4]);
                #pragma unroll
                for (int ni = 0; ni < 8; ni++) {
                    int nc = w * 64 + ni * 8 + r;
                    uint32_t bf[2];
                    bf[0] = f2u(Xt[(k8 * 8 + cq) * LQ2 + nc]);
                    bf[1] = f2u(Xt[(k8 * 8 + cq + 4) * LQ2 + nc]);
                    mma8(acc[ni], af, bf);
                }
            }
        }

        // ---- segment end: write Y as fp16 (RNE) ----
        if (it == 15) {
            float inv0 = 1.0f / lS[r];
            float inv1 = 1.0f / lS[r + 8];
            __half* Y0 = Y + ((long)bcur * SLOTS + r) * HIDDEN;
            __half* Y1 = Y + ((long)bcur * SLOTS + r + 8) * HIDDEN;
            #pragma unroll
            for (int ni = 0; ni < 8; ni++) {
                int col = w * 64 + ni * 8 + 2 * cq;
                *(__half2*)(Y0 + col) = __floats2half2_rn(acc[ni][0] * inv0, acc[ni][1] * inv0);
                *(__half2*)(Y1 + col) = __floats2half2_rn(acc[ni][2] * inv1, acc[ni][3] * inv1);
            }
        }
        __syncthreads();   // protect Xs buffer + Ps/scS/mS/lS before next tile
    }
}

// ---------------- launch ----------------
extern "C" void kernel_launch(void* const* d_in, const int* in_sizes, int n_in,
                              void* d_out, int out_size) {
    const float* X      = (const float*)d_in[0];   // [512,256,1024]
    const float* logits = (const float*)d_in[1];   // [512,256]
    const float* LQ     = (const float*)d_in[2];   // [16,1024]
    const float* Wq     = (const float*)d_in[3];
    const float* bq     = (const float*)d_in[4];
    const float* Wk     = (const float*)d_in[5];
    // d_in[6] = bk: cancels in softmax, unused
    const float* Wv     = (const float*)d_in[7];
    const float* bv     = (const float*)d_in[8];
    const float* Wo     = (const float*)d_in[9];
    const float* bo     = (const float*)d_in[10];
    float* out = (float*)d_out;

    float *lqp, *wqp, *wkp, *wop, *wvp, *q1p, *q2p, *b2p;
    __half *w2hp, *yhp;
    cudaGetSymbolAddress((void**)&lqp,  g_lq);
    cudaGetSymbolAddress((void**)&wqp,  g_wq);
    cudaGetSymbolAddress((void**)&wkp,  g_wk);
    cudaGetSymbolAddress((void**)&wop,  g_wo);
    cudaGetSymbolAddress((void**)&wvp,  g_wv);
    cudaGetSymbolAddress((void**)&q1p,  g_q1);
    cudaGetSymbolAddress((void**)&q2p,  g_q2);
    cudaGetSymbolAddress((void**)&w2hp, g_w2h);
    cudaGetSymbolAddress((void**)&b2p,  g_b2);
    cudaGetSymbolAddress((void**)&yhp,  g_yh);

    // smem opt-in (idempotent)
    cudaFuncSetAttribute((const void*)gemm_cpa<16,64,32,1,4,4,true,true,true,false,1>,
                         cudaFuncAttributeMaxDynamicSharedMemorySize, 51200);
    cudaFuncSetAttribute((const void*)gemm_cpa<16,64,32,1,4,4,false,false,true,false,1>,
                         cudaFuncAttributeMaxDynamicSharedMemorySize, 47104);
    cudaFuncSetAttribute((const void*)gemm_cpa<64,64,32,2,2,3,false,false,false,true,1>,
                         cudaFuncAttributeMaxDynamicSharedMemorySize, 58368);
    cudaFuncSetAttribute((const void*)gemm_h,
                         cudaFuncAttributeMaxDynamicSharedMemorySize, 2 * HSTG * 2);
    cudaFuncSetAttribute((const void*)fused_attn,
                         cudaFuncAttributeMaxDynamicSharedMemorySize, FUSED_SMEM);

    // 0) one-time RNA rounding of weights (one batched launch + tiny LQ)
    k_round4<<<dim3(1024, 4), 256>>>(wqp, Wq, wkp, Wk, wop, Wo, wvp, Wv);
    k_round<<<16, 256>>>(lqp, LQ, SLOTS * HIDDEN / 4);

    // 1) q1 = LQ @ Wq^T + bq    [16,1024]
    gemm_cpa<16, 64, 32, 1, 4, 4, true, true, true, false, 1><<<dim3(16, 1), 128, 51200>>>(
        lqp, wqp, q1p, bq, 16, 1024, 1024);
    // 2) Q2 = q1 @ Wk           [16,1024]
    gemm_cpa<16, 64, 32, 1, 4, 4, false, false, true, false, 1><<<dim3(16, 1), 128, 47104>>>(
        q1p, wkp, q2p, nullptr, 16, 1024, 1024);
    // 3) b2 = Wo @ bv + bo      (exact fp32, raw weights)
    k_b2<<<4, 256>>>(Wo, bv, bo);
    // 4) W2 = Wo @ Wv           [1024,1024], stored fp16 (RNE)
    gemm_cpa<64, 64, 32, 2, 2, 3, false, false, false, true, 1><<<dim3(16, 16), 128, 58368>>>(
        wop, wvp, (float*)w2hp, nullptr, 1024, 1024, 1024);
    // 5) fused attention (persistent): Y[b] = softmax(Q2·X^T/32 + logits) @ X, fp16 out
    fused_attn<<<FGRID, 512, FUSED_SMEM>>>(X, logits, yhp);
    // 6) out = Y @ W2^T + b2    [8192,1024], fp16 mma
    gemm_h<<<dim3(8, 64), 128, 2 * HSTG * 2>>>(
        yhp, w2hp, out, b2p, BSZ * SLOTS, HIDDEN, HIDDEN);
}